// round 3
// baseline (speedup 1.0000x reference)
#include <cuda_runtime.h>

// Problem constants: x shape [3, 5, 32, 64, 32, 32]
#define N_IMGS   30720      // 3*5*32*64
#define N_OUT    480        // 3*5*32
#define PATCHES  64
#define HW       1024       // 32*32

// Per-image "max count" scratch (device global — no allocation allowed).
__device__ int g_counts[N_IMGS];

// ---- union-find in shared memory (Komura equivalence, atomicMin merge) ----

__device__ __forceinline__ int ufind(const int* L, int a) {
    int p = L[a];
    while (p != a) { a = p; p = L[a]; }
    return a;
}

__device__ __forceinline__ void umerge(int* L, int a, int b) {
    while (true) {
        a = ufind(L, a);
        b = ufind(L, b);
        if (a == b) return;
        int mn = min(a, b);
        int mx = max(a, b);
        int old = atomicMin(&L[mx], mn);
        if (old == mx) return;   // successfully linked root mx -> mn
        a = mn;
        b = old;                 // someone else linked mx first; keep merging
    }
}

// One CTA per 32x32 image. 1024 threads, 1 pixel each.
__global__ void __launch_bounds__(1024, 2)
ccl_kernel(const float* __restrict__ x) {
    __shared__ int L[HW];
    __shared__ int cnt[HW];
    __shared__ int warp_max[32];

    const int t = threadIdx.x;
    const size_t base = (size_t)blockIdx.x * HW;

    const bool fg = (x[base + t] != 0.0f);
    L[t] = fg ? t : -1;          // -1 marks background (stable under merges)
    cnt[t] = 0;

    // barrier + foreground population count in one op
    const int nfg = __syncthreads_count(fg);

    if (fg) {
        // right neighbor (same row)
        if ((t & 31) != 31 && L[t + 1] >= 0)  umerge(L, t, t + 1);
        // down neighbor (next row)
        if (t < HW - 32 && L[t + 32] >= 0)    umerge(L, t, t + 32);
    }
    __syncthreads();

    // Count component sizes at the roots.
    if (fg) {
        int root = ufind(L, t);
        atomicAdd(&cnt[root], 1);
    }
    __syncthreads();

    // Block-wide max over cnt[], then fold in the background count.
    int v = cnt[t];
    #pragma unroll
    for (int o = 16; o > 0; o >>= 1)
        v = max(v, __shfl_xor_sync(0xFFFFFFFFu, v, o));
    if ((t & 31) == 0) warp_max[t >> 5] = v;
    __syncthreads();
    if (t < 32) {
        int w = warp_max[t];
        #pragma unroll
        for (int o = 16; o > 0; o >>= 1)
            w = max(w, __shfl_xor_sync(0xFFFFFFFFu, w, o));
        if (t == 0)
            g_counts[blockIdx.x] = max(w, HW - nfg);  // include background label
    }
}

// Sum 64 patch counts per (C,B,Bt), truncating integer divide, write float.
__global__ void reduce_kernel(float* __restrict__ out) {
    int i = blockIdx.x * blockDim.x + threadIdx.x;
    if (i >= N_OUT) return;
    const int* c = &g_counts[i * PATCHES];
    int s = 0;
    #pragma unroll
    for (int p = 0; p < PATCHES; p++) s += c[p];
    out[i] = (float)(s / PATCHES);   // truncating division, matches // on ints
}

extern "C" void kernel_launch(void* const* d_in, const int* in_sizes, int n_in,
                              void* d_out, int out_size) {
    const float* x = (const float*)d_in[0];
    float* out = (float*)d_out;

    ccl_kernel<<<N_IMGS, 1024>>>(x);
    reduce_kernel<<<(N_OUT + 255) / 256, 256>>>(out);
}

// round 6
// speedup vs baseline: 3.6131x; 3.6131x over previous
#include <cuda_runtime.h>

// x shape [3, 5, 32, 64, 32, 32] -> 30720 images of 32x32
#define N_IMGS   30720
#define N_OUT    480
#define PATCHES  64
#define HW       1024
#define WPB      8          // warps (=images) per block
#define MAXRUNS  512        // <= 16 runs/row * 32 rows

__device__ int g_counts[N_IMGS];

// ---- union-find over runs in shared memory ----
__device__ __forceinline__ int ufind(const int* L, int a) {
    int p = L[a];
    while (p != a) { a = p; p = L[a]; }
    return a;
}

__device__ __forceinline__ void umerge(int* L, int a, int b) {
    while (true) {
        a = ufind(L, a);
        b = ufind(L, b);
        if (a == b) return;
        int mn = min(a, b), mx = max(a, b);
        int old = atomicMin(&L[mx], mn);
        if (old == mx) return;
        a = mn; b = old;
    }
}

// One warp per 32x32 image; lane = row.
__global__ void __launch_bounds__(32 * WPB)
ccl_kernel(const float* __restrict__ x) {
    __shared__ int UF[WPB][MAXRUNS];
    __shared__ int CNT[WPB][MAXRUNS];

    const int lane = threadIdx.x & 31;
    const int warp = threadIdx.x >> 5;
    const int img  = blockIdx.x * WPB + warp;     // grid sized exactly
    const float* p = x + (size_t)img * HW;

    // Build row bitmasks: 32 coalesced 128B loads per warp, one ballot each.
    unsigned m = 0;
    #pragma unroll
    for (int r = 0; r < 32; r++) {
        unsigned b = __ballot_sync(0xFFFFFFFFu, p[r * 32 + lane] != 0.0f);
        if (lane == r) m = b;
    }

    // Run starts (LSB-first): bit j starts a run iff m_j=1 and m_{j-1}=0.
    const unsigned start = m & ~(m << 1);
    const int nmine = __popc(start);

    // Exclusive warp scan of run counts -> run id base per row.
    int scan = nmine;
    #pragma unroll
    for (int o = 1; o < 32; o <<= 1) {
        int v = __shfl_up_sync(0xFFFFFFFFu, scan, o);
        if (lane >= o) scan += v;
    }
    const int base  = scan - nmine;
    const int total = __shfl_sync(0xFFFFFFFFu, scan, 31);

    int* uf  = UF[warp];
    int* cnt = CNT[warp];
    for (int i = lane; i < total; i += 32) { uf[i] = i; cnt[i] = 0; }
    __syncwarp();

    // Next-row info (lane 31 has no next row).
    unsigned nm     = __shfl_down_sync(0xFFFFFFFFu, m, 1);
    unsigned nstart = __shfl_down_sync(0xFFFFFFFFu, start, 1);
    int      nbase  = __shfl_down_sync(0xFFFFFFFFu, base, 1);
    if (lane == 31) nm = 0;

    // Union runs overlapping between row and row+1.
    {
        unsigned rem = m;
        int idx = base;
        while (rem) {
            unsigned low   = rem & (unsigned)(-(int)rem);
            unsigned rmask = (rem + low) - low;      // wraps correctly at bit 31
            rem &= ~rmask;
            unsigned ov = rmask & nm;
            unsigned segs = ov & ~(ov << 1);         // starts of overlap segments
            while (segs) {
                int j = __ffs(segs) - 1;
                segs &= segs - 1;
                unsigned below = (2u << j) - 1;      // bits 0..j (j=31 -> all)
                int b = __popc(nstart & below) - 1;  // next-row run containing j
                umerge(uf, idx, nbase + b);
            }
            idx++;
        }
    }
    __syncwarp();

    // Accumulate component sizes at roots.
    {
        unsigned rem = m;
        int idx = base;
        while (rem) {
            unsigned low   = rem & (unsigned)(-(int)rem);
            unsigned rmask = (rem + low) - low;
            rem &= ~rmask;
            int root = ufind(uf, idx);
            atomicAdd(&cnt[root], __popc(rmask));
            idx++;
        }
    }
    __syncwarp();

    // Max component size; fold in background count (label 0 in reference).
    int v = 0;
    for (int i = lane; i < total; i += 32) v = max(v, cnt[i]);
    int bg = 32 - __popc(m);
    #pragma unroll
    for (int o = 16; o > 0; o >>= 1) {
        v  = max(v, __shfl_xor_sync(0xFFFFFFFFu, v, o));
        bg += __shfl_xor_sync(0xFFFFFFFFu, bg, o);
    }
    if (lane == 0) g_counts[img] = max(v, bg);
}

// One warp per output: sum 64 patch counts, truncating divide, write float.
__global__ void reduce_kernel(float* __restrict__ out) {
    const int o = blockIdx.x;
    const int lane = threadIdx.x;
    const int* c = &g_counts[o * PATCHES];
    int s = c[lane] + c[lane + 32];
    #pragma unroll
    for (int sh = 16; sh > 0; sh >>= 1)
        s += __shfl_xor_sync(0xFFFFFFFFu, s, sh);
    if (lane == 0) out[o] = (float)(s / PATCHES);
}

extern "C" void kernel_launch(void* const* d_in, const int* in_sizes, int n_in,
                              void* d_out, int out_size) {
    const float* x = (const float*)d_in[0];
    float* out = (float*)d_out;

    ccl_kernel<<<N_IMGS / WPB, 32 * WPB>>>(x);
    reduce_kernel<<<N_OUT, 32>>>(out);
}